// round 6
// baseline (speedup 1.0000x reference)
#include <cuda_runtime.h>

#define NN   100000
#define EMAX 1600000
#define INC  128
#define HID  64
#define OUTC 32

// Scratch (device globals — no allocation allowed in kernel_launch)
__device__ float g_dinv[NN];
__device__ int   g_cnt[NN];
__device__ int   g_off[NN + 1];
__device__ int   g_cur[NN];
__device__ int2  g_edge2[EMAX];       // CSR-permuted {src, norm-bits} per edge
__device__ float g_h1[NN * HID];      // x @ W1
__device__ float g_o1[NN * HID];      // aggregated layer-1 output (pre-relu)
__device__ float g_h2[NN * OUTC];     // relu(o1) @ W2

// ---------------------------------------------------------------------------
// degree count (int atomics)
// ---------------------------------------------------------------------------
__global__ void k_cnt_init(int* __restrict__ cnt, int n) {
    int i = blockIdx.x * blockDim.x + threadIdx.x;
    if (i < n) cnt[i] = 0;
}

__global__ void k_cnt_edge(const int* __restrict__ dst, int* __restrict__ cnt, int E) {
    int i = blockIdx.x * blockDim.x + threadIdx.x;
    if (i < E) atomicAdd(&cnt[dst[i]], 1);
}

// ---------------------------------------------------------------------------
// Single-block exclusive scan over cnt -> off/cur; also dinv = rsqrt(cnt+1).
// ---------------------------------------------------------------------------
__global__ __launch_bounds__(1024) void k_scan(const int* __restrict__ cnt,
                                               int* __restrict__ off,
                                               int* __restrict__ cur,
                                               float* __restrict__ dinv, int n) {
    __shared__ int sums[1024];
    const int t = threadIdx.x;
    const int chunk = (n + 1023) / 1024;
    const int lo = t * chunk;
    const int hi = min(lo + chunk, n);

    int s = 0;
    for (int i = lo; i < hi; i++) s += cnt[i];
    sums[t] = s;
    __syncthreads();

    for (int ofs = 1; ofs < 1024; ofs <<= 1) {
        int add = (t >= ofs) ? sums[t - ofs] : 0;
        __syncthreads();
        sums[t] += add;
        __syncthreads();
    }

    int run = sums[t] - s;     // exclusive prefix for this chunk
    for (int i = lo; i < hi; i++) {
        off[i] = run;
        cur[i] = run;
        int c = cnt[i];
        run += c;
        dinv[i] = rsqrtf((float)c + 1.0f);   // +1 self loop
    }
    if (t == 1023) off[n] = sums[1023];      // total = E
}

// ---------------------------------------------------------------------------
// CSR build: permute edges into dst-bucketed lists, fused {src, norm} record.
// ---------------------------------------------------------------------------
__global__ void k_build(const int* __restrict__ src, const int* __restrict__ dst,
                        const float* __restrict__ dinv, int* __restrict__ cur,
                        int2* __restrict__ edge2, int E) {
    int e = blockIdx.x * blockDim.x + threadIdx.x;
    if (e >= E) return;
    int s = src[e];
    int d = dst[e];
    int pos = atomicAdd(&cur[d], 1);
    edge2[pos] = make_int2(s, __float_as_int(dinv[s] * dinv[d]));
}

// ---------------------------------------------------------------------------
// Tiled fp32 GEMM: H[M,N] = op(X)[M,K] @ W[K,N], op = optional relu on X load.
// ---------------------------------------------------------------------------
template <int K, int N, int TM, int KT, bool RELU>
__global__ __launch_bounds__(256) void k_gemm(const float* __restrict__ X,
                                              const float* __restrict__ W,
                                              float* __restrict__ H, int M) {
    constexpr int CT  = N / 4;
    constexpr int RT  = 256 / CT;
    constexpr int RPT = TM / RT;
    constexpr int TMP = TM + 1;

    __shared__ float Ws[KT * N];
    __shared__ float Xs[KT * TMP];

    const int t    = threadIdx.x;
    const int row0 = blockIdx.x * TM;
    const int ct   = t % CT;
    const int rt   = t / CT;

    float acc[RPT][4];
#pragma unroll
    for (int r = 0; r < RPT; r++) {
        acc[r][0] = 0.f; acc[r][1] = 0.f; acc[r][2] = 0.f; acc[r][3] = 0.f;
    }

    for (int k0 = 0; k0 < K; k0 += KT) {
        __syncthreads();
        for (int i = t * 4; i < KT * N; i += 1024) {
            *(float4*)&Ws[i] = *(const float4*)&W[k0 * N + i];
        }
        for (int i = t * 4; i < TM * KT; i += 1024) {
            int r  = i / KT;
            int c  = i % KT;
            int gr = row0 + r;
            float4 v = make_float4(0.f, 0.f, 0.f, 0.f);
            if (gr < M) v = *(const float4*)&X[gr * K + k0 + c];
            if (RELU) {
                v.x = fmaxf(v.x, 0.f); v.y = fmaxf(v.y, 0.f);
                v.z = fmaxf(v.z, 0.f); v.w = fmaxf(v.w, 0.f);
            }
            Xs[(c + 0) * TMP + r] = v.x;
            Xs[(c + 1) * TMP + r] = v.y;
            Xs[(c + 2) * TMP + r] = v.z;
            Xs[(c + 3) * TMP + r] = v.w;
        }
        __syncthreads();

#pragma unroll 8
        for (int kk = 0; kk < KT; kk++) {
            float4 w = *(const float4*)&Ws[kk * N + ct * 4];
#pragma unroll
            for (int r = 0; r < RPT; r++) {
                float xv = Xs[kk * TMP + rt * RPT + r];
                acc[r][0] = fmaf(xv, w.x, acc[r][0]);
                acc[r][1] = fmaf(xv, w.y, acc[r][1]);
                acc[r][2] = fmaf(xv, w.z, acc[r][2]);
                acc[r][3] = fmaf(xv, w.w, acc[r][3]);
            }
        }
    }

#pragma unroll
    for (int r = 0; r < RPT; r++) {
        int gr = row0 + rt * RPT + r;
        if (gr < M) {
            float4 o = make_float4(acc[r][0], acc[r][1], acc[r][2], acc[r][3]);
            *(float4*)&H[gr * N + ct * 4] = o;
        }
    }
}

// ---------------------------------------------------------------------------
// Gather aggregation: WARP per node. Lane = (q channel-group, p edge-partition),
// Q*P = 32. Each lane accumulates edges j = off[i]+p step P (x2 unrolled),
// then register shuffle-reduce across p. No atomics, no smem.
// ---------------------------------------------------------------------------
template <int C>
__global__ __launch_bounds__(256) void k_gather(const float* __restrict__ h,
                                                const int* __restrict__ off,
                                                const int2* __restrict__ edge2,
                                                const float* __restrict__ dinv,
                                                const float* __restrict__ b,
                                                float* __restrict__ out, int M) {
    constexpr int Q = C / 4;          // channel-group threads (16 or 8)
    constexpr int P = 32 / Q;         // edge partitions per warp (2 or 4)
    const int lane = threadIdx.x & 31;
    const int warp = threadIdx.x >> 5;
    const int i = blockIdx.x * (256 / 32) + warp;
    if (i >= M) return;

    const int q = lane % Q;
    const int p = lane / Q;

    float4 acc = make_float4(0.f, 0.f, 0.f, 0.f);

    const int j0 = off[i];
    const int j1 = off[i + 1];
    int j = j0 + p;

    // x2 unrolled, stride P
    for (; j + P < j1; j += 2 * P) {
        int2 eA = __ldg(&edge2[j]);
        int2 eB = __ldg(&edge2[j + P]);
        float wA = __int_as_float(eA.y);
        float wB = __int_as_float(eB.y);
        float4 uA = *(const float4*)&h[eA.x * C + q * 4];
        float4 uB = *(const float4*)&h[eB.x * C + q * 4];
        acc.x = fmaf(wA, uA.x, acc.x); acc.y = fmaf(wA, uA.y, acc.y);
        acc.z = fmaf(wA, uA.z, acc.z); acc.w = fmaf(wA, uA.w, acc.w);
        acc.x = fmaf(wB, uB.x, acc.x); acc.y = fmaf(wB, uB.y, acc.y);
        acc.z = fmaf(wB, uB.z, acc.z); acc.w = fmaf(wB, uB.w, acc.w);
    }
    if (j < j1) {
        int2 e = __ldg(&edge2[j]);
        float w = __int_as_float(e.y);
        float4 u = *(const float4*)&h[e.x * C + q * 4];
        acc.x = fmaf(w, u.x, acc.x); acc.y = fmaf(w, u.y, acc.y);
        acc.z = fmaf(w, u.z, acc.z); acc.w = fmaf(w, u.w, acc.w);
    }

    // reduce across edge partitions (lanes q, q+Q, q+2Q, ...)
#pragma unroll
    for (int ofs = Q; ofs < 32; ofs <<= 1) {
        acc.x += __shfl_xor_sync(0xffffffffu, acc.x, ofs);
        acc.y += __shfl_xor_sync(0xffffffffu, acc.y, ofs);
        acc.z += __shfl_xor_sync(0xffffffffu, acc.z, ofs);
        acc.w += __shfl_xor_sync(0xffffffffu, acc.w, ofs);
    }

    if (p == 0) {
        const float di = dinv[i];
        const float s2 = di * di;
        float4 bb = *(const float4*)&b[q * 4];
        float4 v  = *(const float4*)&h[i * C + q * 4];
        acc.x += fmaf(s2, v.x, bb.x);
        acc.y += fmaf(s2, v.y, bb.y);
        acc.z += fmaf(s2, v.z, bb.z);
        acc.w += fmaf(s2, v.w, bb.w);
        *(float4*)&out[i * C + q * 4] = acc;
    }
}

// ---------------------------------------------------------------------------
extern "C" void kernel_launch(void* const* d_in, const int* in_sizes, int n_in,
                              void* d_out, int out_size) {
    const float* x   = (const float*)d_in[0];
    const int*   ei  = (const int*)d_in[1];     // int32 (jax x64 disabled)
    const float* W1  = (const float*)d_in[2];
    const float* b1  = (const float*)d_in[3];
    const float* W2  = (const float*)d_in[4];
    const float* b2  = (const float*)d_in[5];
    float*       out = (float*)d_out;

    const int M = in_sizes[0] / INC;       // 100000
    const int E = in_sizes[1] / 2;         // 1600000
    const int* src = ei;
    const int* dst = ei + E;

    float *dinv, *h1, *o1, *h2;
    int *cnt, *off, *cur;
    int2 *edge2;
    cudaGetSymbolAddress((void**)&dinv,  g_dinv);
    cudaGetSymbolAddress((void**)&cnt,   g_cnt);
    cudaGetSymbolAddress((void**)&off,   g_off);
    cudaGetSymbolAddress((void**)&cur,   g_cur);
    cudaGetSymbolAddress((void**)&edge2, g_edge2);
    cudaGetSymbolAddress((void**)&h1,    g_h1);
    cudaGetSymbolAddress((void**)&o1,    g_o1);
    cudaGetSymbolAddress((void**)&h2,    g_h2);

    const int B = 256;
    const int WPB = 256 / 32;   // warps (nodes) per gather block

    // CSR build + normalization
    k_cnt_init<<<(M + B - 1) / B, B>>>(cnt, M);
    k_cnt_edge<<<(E + B - 1) / B, B>>>(dst, cnt, E);
    k_scan<<<1, 1024>>>(cnt, off, cur, dinv, M);
    k_build<<<(E + B - 1) / B, B>>>(src, dst, dinv, cur, edge2, E);

    // layer 1: h1 = x @ W1 ; o1 = gather(h1)
    k_gemm<INC, HID, 64, 64, false><<<(M + 63) / 64, 256>>>(x, W1, h1, M);
    k_gather<HID><<<(M + WPB - 1) / WPB, B>>>(h1, off, edge2, dinv, b1, o1, M);

    // layer 2: h2 = relu(o1) @ W2 ; out = gather(h2)
    k_gemm<HID, OUTC, 64, 64, true><<<(M + 63) / 64, 256>>>(o1, W2, h2, M);
    k_gather<OUTC><<<(M + WPB - 1) / WPB, B>>>(h2, off, edge2, dinv, b2, out, M);
}

// round 7
// speedup vs baseline: 2.0132x; 2.0132x over previous
#include <cuda_runtime.h>

#define NN   100000
#define EMAX 1600000
#define INC  128
#define HID  64
#define OUTC 32
#define SCB  256                      // scan block size (elements == threads)

// Scratch (device globals — no allocation allowed in kernel_launch)
__device__ float g_dinv[NN];
__device__ int   g_cnt[NN];
__device__ int   g_off[NN + 1];
__device__ int   g_cur[NN];
__device__ int   g_part[(NN + SCB - 1) / SCB + 1];
__device__ int2  g_edge2[EMAX];       // CSR-permuted {src, norm-bits} per edge
__device__ float g_h1[NN * HID];      // x @ W1
__device__ float g_o1[NN * HID];      // aggregated layer-1 output (pre-relu)
__device__ float g_h2[NN * OUTC];     // relu(o1) @ W2

// ---------------------------------------------------------------------------
// degree count (int atomics)
// ---------------------------------------------------------------------------
__global__ void k_cnt_init(int* __restrict__ cnt, int n) {
    int i = blockIdx.x * blockDim.x + threadIdx.x;
    if (i < n) cnt[i] = 0;
}

__global__ void k_cnt_edge(const int* __restrict__ dst, int* __restrict__ cnt, int E) {
    int i = blockIdx.x * blockDim.x + threadIdx.x;
    if (i < E) atomicAdd(&cnt[dst[i]], 1);
}

// ---------------------------------------------------------------------------
// Phase 1: per-block partial sums of cnt (coalesced, full chip)
// ---------------------------------------------------------------------------
__global__ __launch_bounds__(SCB) void k_part(const int* __restrict__ cnt,
                                              int* __restrict__ part, int n) {
    __shared__ int wsum[SCB / 32];
    const int i = blockIdx.x * SCB + threadIdx.x;
    const int lane = threadIdx.x & 31, wid = threadIdx.x >> 5;
    int v = (i < n) ? cnt[i] : 0;
#pragma unroll
    for (int ofs = 16; ofs > 0; ofs >>= 1)
        v += __shfl_down_sync(0xffffffffu, v, ofs);
    if (lane == 0) wsum[wid] = v;
    __syncthreads();
    if (wid == 0) {
        int w = (lane < SCB / 32) ? wsum[lane] : 0;
#pragma unroll
        for (int ofs = 16; ofs > 0; ofs >>= 1)
            w += __shfl_down_sync(0xffffffffu, w, ofs);
        if (lane == 0) part[blockIdx.x] = w;
    }
}

// ---------------------------------------------------------------------------
// Phase 2: single-block exclusive scan over block partials (tiny: ~391 values)
// ---------------------------------------------------------------------------
__global__ __launch_bounds__(1024) void k_scan_part(int* __restrict__ part,
                                                    int* __restrict__ off,
                                                    int nb, int n) {
    __shared__ int s[1024];
    const int t = threadIdx.x;
    int v = (t < nb) ? part[t] : 0;
    s[t] = v;
    __syncthreads();
    for (int ofs = 1; ofs < 1024; ofs <<= 1) {
        int add = (t >= ofs) ? s[t - ofs] : 0;
        __syncthreads();
        s[t] += add;
        __syncthreads();
    }
    if (t < nb) part[t] = s[t] - v;          // exclusive block offset
    if (t == 1023) off[n] = s[1023];         // total = E
}

// ---------------------------------------------------------------------------
// Phase 3: block-local exclusive scan + apply block offset; write off/cur/dinv.
// ---------------------------------------------------------------------------
__global__ __launch_bounds__(SCB) void k_apply(const int* __restrict__ cnt,
                                               const int* __restrict__ part,
                                               int* __restrict__ off,
                                               int* __restrict__ cur,
                                               float* __restrict__ dinv, int n) {
    __shared__ int wtot[SCB / 32];
    const int i = blockIdx.x * SCB + threadIdx.x;
    const int lane = threadIdx.x & 31, wid = threadIdx.x >> 5;
    int c = (i < n) ? cnt[i] : 0;

    // inclusive warp scan
    int v = c;
#pragma unroll
    for (int ofs = 1; ofs < 32; ofs <<= 1) {
        int u = __shfl_up_sync(0xffffffffu, v, ofs);
        if (lane >= ofs) v += u;
    }
    if (lane == 31) wtot[wid] = v;
    __syncthreads();
    if (wid == 0) {
        int w = (lane < SCB / 32) ? wtot[lane] : 0;
#pragma unroll
        for (int ofs = 1; ofs < SCB / 32; ofs <<= 1) {
            int u = __shfl_up_sync(0xffffffffu, w, ofs);
            if (lane >= ofs) w += u;
        }
        if (lane < SCB / 32) wtot[lane] = w;
    }
    __syncthreads();

    int excl = v - c + (wid > 0 ? wtot[wid - 1] : 0) + part[blockIdx.x];
    if (i < n) {
        off[i]  = excl;
        cur[i]  = excl;
        dinv[i] = rsqrtf((float)c + 1.0f);   // +1 self loop
    }
}

// ---------------------------------------------------------------------------
// CSR build: permute edges into dst-bucketed lists, fused {src, norm} record.
// ---------------------------------------------------------------------------
__global__ void k_build(const int* __restrict__ src, const int* __restrict__ dst,
                        const float* __restrict__ dinv, int* __restrict__ cur,
                        int2* __restrict__ edge2, int E) {
    int e = blockIdx.x * blockDim.x + threadIdx.x;
    if (e >= E) return;
    int s = src[e];
    int d = dst[e];
    int pos = atomicAdd(&cur[d], 1);
    edge2[pos] = make_int2(s, __float_as_int(dinv[s] * dinv[d]));
}

// ---------------------------------------------------------------------------
// Tiled fp32 GEMM: H[M,N] = op(X)[M,K] @ W[K,N], op = optional relu on X load.
// ---------------------------------------------------------------------------
template <int K, int N, int TM, int KT, bool RELU>
__global__ __launch_bounds__(256) void k_gemm(const float* __restrict__ X,
                                              const float* __restrict__ W,
                                              float* __restrict__ H, int M) {
    constexpr int CT  = N / 4;
    constexpr int RT  = 256 / CT;
    constexpr int RPT = TM / RT;
    constexpr int TMP = TM + 1;

    __shared__ float Ws[KT * N];
    __shared__ float Xs[KT * TMP];

    const int t    = threadIdx.x;
    const int row0 = blockIdx.x * TM;
    const int ct   = t % CT;
    const int rt   = t / CT;

    float acc[RPT][4];
#pragma unroll
    for (int r = 0; r < RPT; r++) {
        acc[r][0] = 0.f; acc[r][1] = 0.f; acc[r][2] = 0.f; acc[r][3] = 0.f;
    }

    for (int k0 = 0; k0 < K; k0 += KT) {
        __syncthreads();
        for (int i = t * 4; i < KT * N; i += 1024) {
            *(float4*)&Ws[i] = *(const float4*)&W[k0 * N + i];
        }
        for (int i = t * 4; i < TM * KT; i += 1024) {
            int r  = i / KT;
            int c  = i % KT;
            int gr = row0 + r;
            float4 v = make_float4(0.f, 0.f, 0.f, 0.f);
            if (gr < M) v = *(const float4*)&X[gr * K + k0 + c];
            if (RELU) {
                v.x = fmaxf(v.x, 0.f); v.y = fmaxf(v.y, 0.f);
                v.z = fmaxf(v.z, 0.f); v.w = fmaxf(v.w, 0.f);
            }
            Xs[(c + 0) * TMP + r] = v.x;
            Xs[(c + 1) * TMP + r] = v.y;
            Xs[(c + 2) * TMP + r] = v.z;
            Xs[(c + 3) * TMP + r] = v.w;
        }
        __syncthreads();

#pragma unroll 8
        for (int kk = 0; kk < KT; kk++) {
            float4 w = *(const float4*)&Ws[kk * N + ct * 4];
#pragma unroll
            for (int r = 0; r < RPT; r++) {
                float xv = Xs[kk * TMP + rt * RPT + r];
                acc[r][0] = fmaf(xv, w.x, acc[r][0]);
                acc[r][1] = fmaf(xv, w.y, acc[r][1]);
                acc[r][2] = fmaf(xv, w.z, acc[r][2]);
                acc[r][3] = fmaf(xv, w.w, acc[r][3]);
            }
        }
    }

#pragma unroll
    for (int r = 0; r < RPT; r++) {
        int gr = row0 + rt * RPT + r;
        if (gr < M) {
            float4 o = make_float4(acc[r][0], acc[r][1], acc[r][2], acc[r][3]);
            *(float4*)&H[gr * N + ct * 4] = o;
        }
    }
}

// ---------------------------------------------------------------------------
// Gather aggregation: WARP per node. Lane = (q channel-group, p edge-partition),
// Q*P = 32. Shuffle-reduce across p. No atomics, no smem.
// ---------------------------------------------------------------------------
template <int C>
__global__ __launch_bounds__(256) void k_gather(const float* __restrict__ h,
                                                const int* __restrict__ off,
                                                const int2* __restrict__ edge2,
                                                const float* __restrict__ dinv,
                                                const float* __restrict__ b,
                                                float* __restrict__ out, int M) {
    constexpr int Q = C / 4;          // channel-group threads (16 or 8)
    constexpr int P = 32 / Q;         // edge partitions per warp (2 or 4)
    const int lane = threadIdx.x & 31;
    const int warp = threadIdx.x >> 5;
    const int i = blockIdx.x * (256 / 32) + warp;
    if (i >= M) return;

    const int q = lane % Q;
    const int p = lane / Q;

    float4 acc = make_float4(0.f, 0.f, 0.f, 0.f);

    const int j1 = off[i + 1];
    int j = off[i] + p;

    for (; j + P < j1; j += 2 * P) {
        int2 eA = __ldg(&edge2[j]);
        int2 eB = __ldg(&edge2[j + P]);
        float wA = __int_as_float(eA.y);
        float wB = __int_as_float(eB.y);
        float4 uA = *(const float4*)&h[eA.x * C + q * 4];
        float4 uB = *(const float4*)&h[eB.x * C + q * 4];
        acc.x = fmaf(wA, uA.x, acc.x); acc.y = fmaf(wA, uA.y, acc.y);
        acc.z = fmaf(wA, uA.z, acc.z); acc.w = fmaf(wA, uA.w, acc.w);
        acc.x = fmaf(wB, uB.x, acc.x); acc.y = fmaf(wB, uB.y, acc.y);
        acc.z = fmaf(wB, uB.z, acc.z); acc.w = fmaf(wB, uB.w, acc.w);
    }
    if (j < j1) {
        int2 e = __ldg(&edge2[j]);
        float w = __int_as_float(e.y);
        float4 u = *(const float4*)&h[e.x * C + q * 4];
        acc.x = fmaf(w, u.x, acc.x); acc.y = fmaf(w, u.y, acc.y);
        acc.z = fmaf(w, u.z, acc.z); acc.w = fmaf(w, u.w, acc.w);
    }

#pragma unroll
    for (int ofs = Q; ofs < 32; ofs <<= 1) {
        acc.x += __shfl_xor_sync(0xffffffffu, acc.x, ofs);
        acc.y += __shfl_xor_sync(0xffffffffu, acc.y, ofs);
        acc.z += __shfl_xor_sync(0xffffffffu, acc.z, ofs);
        acc.w += __shfl_xor_sync(0xffffffffu, acc.w, ofs);
    }

    if (p == 0) {
        const float di = dinv[i];
        const float s2 = di * di;
        float4 bb = *(const float4*)&b[q * 4];
        float4 v  = *(const float4*)&h[i * C + q * 4];
        acc.x += fmaf(s2, v.x, bb.x);
        acc.y += fmaf(s2, v.y, bb.y);
        acc.z += fmaf(s2, v.z, bb.z);
        acc.w += fmaf(s2, v.w, bb.w);
        *(float4*)&out[i * C + q * 4] = acc;
    }
}

// ---------------------------------------------------------------------------
extern "C" void kernel_launch(void* const* d_in, const int* in_sizes, int n_in,
                              void* d_out, int out_size) {
    const float* x   = (const float*)d_in[0];
    const int*   ei  = (const int*)d_in[1];     // int32 (jax x64 disabled)
    const float* W1  = (const float*)d_in[2];
    const float* b1  = (const float*)d_in[3];
    const float* W2  = (const float*)d_in[4];
    const float* b2  = (const float*)d_in[5];
    float*       out = (float*)d_out;

    const int M = in_sizes[0] / INC;       // 100000
    const int E = in_sizes[1] / 2;         // 1600000
    const int* src = ei;
    const int* dst = ei + E;

    float *dinv, *h1, *o1, *h2;
    int *cnt, *off, *cur, *part;
    int2 *edge2;
    cudaGetSymbolAddress((void**)&dinv,  g_dinv);
    cudaGetSymbolAddress((void**)&cnt,   g_cnt);
    cudaGetSymbolAddress((void**)&off,   g_off);
    cudaGetSymbolAddress((void**)&cur,   g_cur);
    cudaGetSymbolAddress((void**)&part,  g_part);
    cudaGetSymbolAddress((void**)&edge2, g_edge2);
    cudaGetSymbolAddress((void**)&h1,    g_h1);
    cudaGetSymbolAddress((void**)&o1,    g_o1);
    cudaGetSymbolAddress((void**)&h2,    g_h2);

    const int B = 256;
    const int WPB = 256 / 32;              // warps (nodes) per gather block
    const int NB = (M + SCB - 1) / SCB;    // scan blocks

    // CSR build + normalization (3-phase parallel scan)
    k_cnt_init<<<(M + B - 1) / B, B>>>(cnt, M);
    k_cnt_edge<<<(E + B - 1) / B, B>>>(dst, cnt, E);
    k_part<<<NB, SCB>>>(cnt, part, M);
    k_scan_part<<<1, 1024>>>(part, off, NB, M);
    k_apply<<<NB, SCB>>>(cnt, part, off, cur, dinv, M);
    k_build<<<(E + B - 1) / B, B>>>(src, dst, dinv, cur, edge2, E);

    // layer 1: h1 = x @ W1 ; o1 = gather(h1)
    k_gemm<INC, HID, 64, 64, false><<<(M + 63) / 64, 256>>>(x, W1, h1, M);
    k_gather<HID><<<(M + WPB - 1) / WPB, B>>>(h1, off, edge2, dinv, b1, o1, M);

    // layer 2: h2 = relu(o1) @ W2 ; out = gather(h2)
    k_gemm<HID, OUTC, 64, 64, true><<<(M + 63) / 64, 256>>>(o1, W2, h2, M);
    k_gather<OUTC><<<(M + WPB - 1) / WPB, B>>>(h2, off, edge2, dinv, b2, out, M);
}

// round 8
// speedup vs baseline: 2.1996x; 1.0926x over previous
#include <cuda_runtime.h>

#define NN   100000
#define EMAX 1600000
#define INC  128
#define HID  64
#define OUTC 32
#define SCB  256                      // scan block size (elements == threads)

// Scratch (device globals — no allocation allowed in kernel_launch)
__device__ float g_dinv[NN];
__device__ int   g_cnt[NN];
__device__ int   g_off[NN + 1];
__device__ int   g_cur[NN];
__device__ int   g_part[(NN + SCB - 1) / SCB + 1];
__device__ int2  g_edge2[EMAX];       // CSR-permuted {src, norm-bits} per edge
__device__ float g_h1[NN * HID];      // x @ W1
__device__ float g_o1[NN * HID];      // aggregated layer-1 output (pre-relu)
__device__ float g_h2[NN * OUTC];     // relu(o1) @ W2

// ---------------------------------------------------------------------------
// degree count (int atomics)
// ---------------------------------------------------------------------------
__global__ void k_cnt_init(int* __restrict__ cnt, int n) {
    int i = blockIdx.x * blockDim.x + threadIdx.x;
    if (i < n) cnt[i] = 0;
}

__global__ void k_cnt_edge(const int* __restrict__ dst, int* __restrict__ cnt, int E) {
    int i = blockIdx.x * blockDim.x + threadIdx.x;
    if (i * 4 >= E) return;
    if (i * 4 + 3 < E) {
        int4 d4 = *(const int4*)&dst[i * 4];
        atomicAdd(&cnt[d4.x], 1);
        atomicAdd(&cnt[d4.y], 1);
        atomicAdd(&cnt[d4.z], 1);
        atomicAdd(&cnt[d4.w], 1);
    } else {
        for (int e = i * 4; e < E; e++) atomicAdd(&cnt[dst[e]], 1);
    }
}

// ---------------------------------------------------------------------------
// Phase 1: per-block partial sums of cnt (coalesced, full chip)
// ---------------------------------------------------------------------------
__global__ __launch_bounds__(SCB) void k_part(const int* __restrict__ cnt,
                                              int* __restrict__ part, int n) {
    __shared__ int wsum[SCB / 32];
    const int i = blockIdx.x * SCB + threadIdx.x;
    const int lane = threadIdx.x & 31, wid = threadIdx.x >> 5;
    int v = (i < n) ? cnt[i] : 0;
#pragma unroll
    for (int ofs = 16; ofs > 0; ofs >>= 1)
        v += __shfl_down_sync(0xffffffffu, v, ofs);
    if (lane == 0) wsum[wid] = v;
    __syncthreads();
    if (wid == 0) {
        int w = (lane < SCB / 32) ? wsum[lane] : 0;
#pragma unroll
        for (int ofs = 16; ofs > 0; ofs >>= 1)
            w += __shfl_down_sync(0xffffffffu, w, ofs);
        if (lane == 0) part[blockIdx.x] = w;
    }
}

// ---------------------------------------------------------------------------
// Phase 2: single-block exclusive scan over block partials (tiny: ~391 values)
// ---------------------------------------------------------------------------
__global__ __launch_bounds__(1024) void k_scan_part(int* __restrict__ part,
                                                    int* __restrict__ off,
                                                    int nb, int n) {
    __shared__ int s[1024];
    const int t = threadIdx.x;
    int v = (t < nb) ? part[t] : 0;
    s[t] = v;
    __syncthreads();
    for (int ofs = 1; ofs < 1024; ofs <<= 1) {
        int add = (t >= ofs) ? s[t - ofs] : 0;
        __syncthreads();
        s[t] += add;
        __syncthreads();
    }
    if (t < nb) part[t] = s[t] - v;          // exclusive block offset
    if (t == 1023) off[n] = s[1023];         // total = E
}

// ---------------------------------------------------------------------------
// Phase 3: block-local exclusive scan + apply block offset; write off/cur/dinv.
// ---------------------------------------------------------------------------
__global__ __launch_bounds__(SCB) void k_apply(const int* __restrict__ cnt,
                                               const int* __restrict__ part,
                                               int* __restrict__ off,
                                               int* __restrict__ cur,
                                               float* __restrict__ dinv, int n) {
    __shared__ int wtot[SCB / 32];
    const int i = blockIdx.x * SCB + threadIdx.x;
    const int lane = threadIdx.x & 31, wid = threadIdx.x >> 5;
    int c = (i < n) ? cnt[i] : 0;

    int v = c;
#pragma unroll
    for (int ofs = 1; ofs < 32; ofs <<= 1) {
        int u = __shfl_up_sync(0xffffffffu, v, ofs);
        if (lane >= ofs) v += u;
    }
    if (lane == 31) wtot[wid] = v;
    __syncthreads();
    if (wid == 0) {
        int w = (lane < SCB / 32) ? wtot[lane] : 0;
#pragma unroll
        for (int ofs = 1; ofs < SCB / 32; ofs <<= 1) {
            int u = __shfl_up_sync(0xffffffffu, w, ofs);
            if (lane >= ofs) w += u;
        }
        if (lane < SCB / 32) wtot[lane] = w;
    }
    __syncthreads();

    int excl = v - c + (wid > 0 ? wtot[wid - 1] : 0) + part[blockIdx.x];
    if (i < n) {
        off[i]  = excl;
        cur[i]  = excl;
        dinv[i] = rsqrtf((float)c + 1.0f);   // +1 self loop
    }
}

// ---------------------------------------------------------------------------
// CSR build: permute edges into dst-bucketed lists, fused {src, norm} record.
// ---------------------------------------------------------------------------
__global__ void k_build(const int* __restrict__ src, const int* __restrict__ dst,
                        const float* __restrict__ dinv, int* __restrict__ cur,
                        int2* __restrict__ edge2, int E) {
    int e = blockIdx.x * blockDim.x + threadIdx.x;
    if (e >= E) return;
    int s = src[e];
    int d = dst[e];
    int pos = atomicAdd(&cur[d], 1);
    edge2[pos] = make_int2(s, __float_as_int(dinv[s] * dinv[d]));
}

// ---------------------------------------------------------------------------
// Tiled fp32 GEMM: H[M,N] = op(X)[M,K] @ W[K,N], op = optional relu on X load.
// TM=128 rows/block, 256 threads, RPT rows x 4 cols per thread.
// Xs transposed with pad 4 so inner-loop reads are LDS.128.
// ---------------------------------------------------------------------------
template <int K, int N, int TM, int KT, bool RELU>
__global__ __launch_bounds__(256) void k_gemm(const float* __restrict__ X,
                                              const float* __restrict__ W,
                                              float* __restrict__ H, int M) {
    constexpr int CT  = N / 4;        // threads along N (4 cols each)
    constexpr int RT  = 256 / CT;     // threads along M
    constexpr int RPT = TM / RT;      // rows per thread (8 for N=64, 4 for N=32)
    constexpr int TMP = TM + 4;       // padded (mult of 4) for aligned LDS.128

    __shared__ float Ws[KT * N];
    __shared__ float Xs[KT * TMP];

    const int t    = threadIdx.x;
    const int row0 = blockIdx.x * TM;
    const int ct   = t % CT;
    const int rt   = t / CT;

    float acc[RPT][4];
#pragma unroll
    for (int r = 0; r < RPT; r++) {
        acc[r][0] = 0.f; acc[r][1] = 0.f; acc[r][2] = 0.f; acc[r][3] = 0.f;
    }

    for (int k0 = 0; k0 < K; k0 += KT) {
        __syncthreads();
        for (int i = t * 4; i < KT * N; i += 1024) {
            *(float4*)&Ws[i] = *(const float4*)&W[k0 * N + i];
        }
        for (int i = t * 4; i < TM * KT; i += 1024) {
            int r  = i / KT;
            int c  = i % KT;
            int gr = row0 + r;
            float4 v = make_float4(0.f, 0.f, 0.f, 0.f);
            if (gr < M) v = *(const float4*)&X[gr * K + k0 + c];
            if (RELU) {
                v.x = fmaxf(v.x, 0.f); v.y = fmaxf(v.y, 0.f);
                v.z = fmaxf(v.z, 0.f); v.w = fmaxf(v.w, 0.f);
            }
            Xs[(c + 0) * TMP + r] = v.x;
            Xs[(c + 1) * TMP + r] = v.y;
            Xs[(c + 2) * TMP + r] = v.z;
            Xs[(c + 3) * TMP + r] = v.w;
        }
        __syncthreads();

#pragma unroll 8
        for (int kk = 0; kk < KT; kk++) {
            float4 w = *(const float4*)&Ws[kk * N + ct * 4];
            float xv[RPT];
#pragma unroll
            for (int rr = 0; rr < RPT; rr += 4) {
                float4 x4 = *(const float4*)&Xs[kk * TMP + rt * RPT + rr];
                xv[rr + 0] = x4.x; xv[rr + 1] = x4.y;
                xv[rr + 2] = x4.z; xv[rr + 3] = x4.w;
            }
#pragma unroll
            for (int r = 0; r < RPT; r++) {
                acc[r][0] = fmaf(xv[r], w.x, acc[r][0]);
                acc[r][1] = fmaf(xv[r], w.y, acc[r][1]);
                acc[r][2] = fmaf(xv[r], w.z, acc[r][2]);
                acc[r][3] = fmaf(xv[r], w.w, acc[r][3]);
            }
        }
    }

#pragma unroll
    for (int r = 0; r < RPT; r++) {
        int gr = row0 + rt * RPT + r;
        if (gr < M) {
            float4 o = make_float4(acc[r][0], acc[r][1], acc[r][2], acc[r][3]);
            *(float4*)&H[gr * N + ct * 4] = o;
        }
    }
}

// ---------------------------------------------------------------------------
// Gather aggregation: WARP per node. Lane = (q channel-group, p edge-partition),
// Q*P = 32. Shuffle-reduce across p. No atomics, no smem.
// ---------------------------------------------------------------------------
template <int C>
__global__ __launch_bounds__(256) void k_gather(const float* __restrict__ h,
                                                const int* __restrict__ off,
                                                const int2* __restrict__ edge2,
                                                const float* __restrict__ dinv,
                                                const float* __restrict__ b,
                                                float* __restrict__ out, int M) {
    constexpr int Q = C / 4;          // channel-group threads (16 or 8)
    constexpr int P = 32 / Q;         // edge partitions per warp (2 or 4)
    const int lane = threadIdx.x & 31;
    const int warp = threadIdx.x >> 5;
    const int i = blockIdx.x * (256 / 32) + warp;
    if (i >= M) return;

    const int q = lane % Q;
    const int p = lane / Q;

    float4 acc = make_float4(0.f, 0.f, 0.f, 0.f);

    const int j1 = off[i + 1];
    int j = off[i] + p;

    for (; j + P < j1; j += 2 * P) {
        int2 eA = __ldg(&edge2[j]);
        int2 eB = __ldg(&edge2[j + P]);
        float wA = __int_as_float(eA.y);
        float wB = __int_as_float(eB.y);
        float4 uA = *(const float4*)&h[eA.x * C + q * 4];
        float4 uB = *(const float4*)&h[eB.x * C + q * 4];
        acc.x = fmaf(wA, uA.x, acc.x); acc.y = fmaf(wA, uA.y, acc.y);
        acc.z = fmaf(wA, uA.z, acc.z); acc.w = fmaf(wA, uA.w, acc.w);
        acc.x = fmaf(wB, uB.x, acc.x); acc.y = fmaf(wB, uB.y, acc.y);
        acc.z = fmaf(wB, uB.z, acc.z); acc.w = fmaf(wB, uB.w, acc.w);
    }
    if (j < j1) {
        int2 e = __ldg(&edge2[j]);
        float w = __int_as_float(e.y);
        float4 u = *(const float4*)&h[e.x * C + q * 4];
        acc.x = fmaf(w, u.x, acc.x); acc.y = fmaf(w, u.y, acc.y);
        acc.z = fmaf(w, u.z, acc.z); acc.w = fmaf(w, u.w, acc.w);
    }

#pragma unroll
    for (int ofs = Q; ofs < 32; ofs <<= 1) {
        acc.x += __shfl_xor_sync(0xffffffffu, acc.x, ofs);
        acc.y += __shfl_xor_sync(0xffffffffu, acc.y, ofs);
        acc.z += __shfl_xor_sync(0xffffffffu, acc.z, ofs);
        acc.w += __shfl_xor_sync(0xffffffffu, acc.w, ofs);
    }

    if (p == 0) {
        const float di = dinv[i];
        const float s2 = di * di;
        float4 bb = *(const float4*)&b[q * 4];
        float4 v  = *(const float4*)&h[i * C + q * 4];
        acc.x += fmaf(s2, v.x, bb.x);
        acc.y += fmaf(s2, v.y, bb.y);
        acc.z += fmaf(s2, v.z, bb.z);
        acc.w += fmaf(s2, v.w, bb.w);
        *(float4*)&out[i * C + q * 4] = acc;
    }
}

// ---------------------------------------------------------------------------
extern "C" void kernel_launch(void* const* d_in, const int* in_sizes, int n_in,
                              void* d_out, int out_size) {
    const float* x   = (const float*)d_in[0];
    const int*   ei  = (const int*)d_in[1];     // int32 (jax x64 disabled)
    const float* W1  = (const float*)d_in[2];
    const float* b1  = (const float*)d_in[3];
    const float* W2  = (const float*)d_in[4];
    const float* b2  = (const float*)d_in[5];
    float*       out = (float*)d_out;

    const int M = in_sizes[0] / INC;       // 100000
    const int E = in_sizes[1] / 2;         // 1600000
    const int* src = ei;
    const int* dst = ei + E;

    float *dinv, *h1, *o1, *h2;
    int *cnt, *off, *cur, *part;
    int2 *edge2;
    cudaGetSymbolAddress((void**)&dinv,  g_dinv);
    cudaGetSymbolAddress((void**)&cnt,   g_cnt);
    cudaGetSymbolAddress((void**)&off,   g_off);
    cudaGetSymbolAddress((void**)&cur,   g_cur);
    cudaGetSymbolAddress((void**)&part,  g_part);
    cudaGetSymbolAddress((void**)&edge2, g_edge2);
    cudaGetSymbolAddress((void**)&h1,    g_h1);
    cudaGetSymbolAddress((void**)&o1,    g_o1);
    cudaGetSymbolAddress((void**)&h2,    g_h2);

    // Side stream + events for fork/join (created once; creation is not a
    // device-memory allocation and happens outside any captured region on
    // the first, non-captured call).
    static cudaStream_t sA = nullptr;
    static cudaEvent_t  evF = nullptr, evJ = nullptr;
    if (sA == nullptr) {
        cudaStreamCreateWithFlags(&sA, cudaStreamNonBlocking);
        cudaEventCreateWithFlags(&evF, cudaEventDisableTiming);
        cudaEventCreateWithFlags(&evJ, cudaEventDisableTiming);
    }

    const int B = 256;
    const int WPB = 256 / 32;              // warps (nodes) per gather block
    const int NB = (M + SCB - 1) / SCB;    // scan blocks

    // Fork: CSR build chain on sA, gemm1 on main stream (independent).
    cudaEventRecord(evF, 0);
    cudaStreamWaitEvent(sA, evF, 0);

    k_cnt_init<<<(M + B - 1) / B, B, 0, sA>>>(cnt, M);
    k_cnt_edge<<<(E / 4 + B - 1) / B, B, 0, sA>>>(dst, cnt, E);
    k_part<<<NB, SCB, 0, sA>>>(cnt, part, M);
    k_scan_part<<<1, 1024, 0, sA>>>(part, off, NB, M);
    k_apply<<<NB, SCB, 0, sA>>>(cnt, part, off, cur, dinv, M);
    k_build<<<(E + B - 1) / B, B, 0, sA>>>(src, dst, dinv, cur, edge2, E);
    cudaEventRecord(evJ, sA);

    // layer 1 GEMM runs concurrently with the CSR build
    k_gemm<INC, HID, 128, 32, false><<<(M + 127) / 128, 256>>>(x, W1, h1, M);

    // Join, then the serial tail
    cudaStreamWaitEvent(0, evJ, 0);
    k_gather<HID><<<(M + WPB - 1) / WPB, B>>>(h1, off, edge2, dinv, b1, o1, M);
    k_gemm<HID, OUTC, 128, 32, true><<<(M + 127) / 128, 256>>>(o1, W2, h2, M);
    k_gather<OUTC><<<(M + WPB - 1) / WPB, B>>>(h2, off, edge2, dinv, b2, out, M);
}